// round 17
// baseline (speedup 1.0000x reference)
#include <cuda_runtime.h>
#include <cuda_fp16.h>
#include <math.h>
#include <cstdint>

#define C_DIM 512
#define N_TOK 4096
#define HEADS 8
#define HDIM  64
#define KSCALE 0.18033688011112042f   // 0.125 * log2(e)

// ---------------- device scratch (fp16 hi/lo where needed) ----------------
__device__ __align__(16) __half g_xh[C_DIM * N_TOK], g_xl[C_DIM * N_TOK];
__device__ __align__(16) __half g_wqh[C_DIM * C_DIM];
__device__ __align__(16) __half g_wkh[C_DIM * C_DIM];
__device__ __align__(16) __half g_wvh[C_DIM * C_DIM];
__device__ __align__(16) __half g_woh[C_DIM * C_DIM];
__device__ __align__(16) __half g_qh[C_DIM * N_TOK];
__device__ __align__(16) __half g_kh[C_DIM * N_TOK], g_kl[C_DIM * N_TOK];
__device__ __align__(16) __half g_vh[C_DIM * N_TOK], g_vl[C_DIM * N_TOK];
__device__ __align__(16) __half g_sh[C_DIM * N_TOK], g_sl[C_DIM * N_TOK];

// ---------------- helpers ----------------
__device__ __forceinline__ uint32_t smem_u32(const void* p) {
    uint32_t a;
    asm("{ .reg .u64 t; cvta.to.shared.u64 t, %1; cvt.u32.u64 %0, t; }" : "=r"(a) : "l"(p));
    return a;
}
__device__ __forceinline__ uint32_t packh(float lo, float hi) {   // low half = lo
    __half2 h = __floats2half2_rn(lo, hi);
    return *reinterpret_cast<uint32_t*>(&h);
}
__device__ __forceinline__ float hlo(uint32_t p) {
    __half2 h = *reinterpret_cast<__half2*>(&p);
    return __low2float(h);
}
__device__ __forceinline__ float hhi(uint32_t p) {
    __half2 h = *reinterpret_cast<__half2*>(&p);
    return __high2float(h);
}
__device__ __forceinline__ float ex2f(float x) {
    float r; asm("ex2.approx.f32 %0, %1;" : "=f"(r) : "f"(x)); return r;
}

#define LDSM4(R, a) \
    asm volatile("ldmatrix.sync.aligned.m8n8.x4.shared.b16 {%0,%1,%2,%3}, [%4];" \
        : "=r"((R)[0]), "=r"((R)[1]), "=r"((R)[2]), "=r"((R)[3]) : "r"(a) : "memory")
#define LDSM4T(R, a) \
    asm volatile("ldmatrix.sync.aligned.m8n8.x4.trans.shared.b16 {%0,%1,%2,%3}, [%4];" \
        : "=r"((R)[0]), "=r"((R)[1]), "=r"((R)[2]), "=r"((R)[3]) : "r"(a) : "memory")
#define MMA(C, A, B) \
    asm volatile("mma.sync.aligned.m16n8k16.row.col.f32.f16.f16.f32 " \
        "{%0,%1,%2,%3}, {%4,%5,%6,%7}, {%8,%9}, {%0,%1,%2,%3};" \
        : "+f"((C)[0]), "+f"((C)[1]), "+f"((C)[2]), "+f"((C)[3]) \
        : "r"((A)[0]), "r"((A)[1]), "r"((A)[2]), "r"((A)[3]), "r"((B)[0]), "r"((B)[1]))
#define CP16(dst, src) \
    asm volatile("cp.async.cg.shared.global [%0], [%1], 16;" :: "r"(dst), "l"(src))
#define CP_COMMIT() asm volatile("cp.async.commit_group;" ::: "memory")
#define CP_WAIT0()  asm volatile("cp.async.wait_group 0;" ::: "memory")
#define CP_WAIT1()  asm volatile("cp.async.wait_group 1;" ::: "memory")
#define CP_WAIT2()  asm volatile("cp.async.wait_group 2;" ::: "memory")

// =====================================================================
// fused split: X -> hi/lo; 4 weight matrices -> hi only
// =====================================================================
#define NX4 (C_DIM * N_TOK / 4)    // 524288
#define NW4 (C_DIM * C_DIM / 4)    // 65536
__global__ __launch_bounds__(256) void split_all(
    const float* __restrict__ x,  const float* __restrict__ qw,
    const float* __restrict__ kw, const float* __restrict__ vw,
    const float* __restrict__ ow)
{
    int i = blockIdx.x * 256 + threadIdx.x;
    if (i < NX4) {
        float4 v = ((const float4*)x)[i];
        uint32_t h01 = packh(v.x, v.y), h23 = packh(v.z, v.w);
        uint32_t l01 = packh(v.x - hlo(h01), v.y - hhi(h01));
        uint32_t l23 = packh(v.z - hlo(h23), v.w - hhi(h23));
        ((uint2*)g_xh)[i] = make_uint2(h01, h23);
        ((uint2*)g_xl)[i] = make_uint2(l01, l23);
    } else {
        int j = i - NX4;
        int w = j >> 16;  int idx = j & (NW4 - 1);
        const float* src; __half* oh; float scale = 1.0f;
        if      (w == 0) { src = qw; oh = g_wqh; }
        else if (w == 1) { src = kw; oh = g_wkh; scale = KSCALE; }
        else if (w == 2) { src = vw; oh = g_wvh; }
        else             { src = ow; oh = g_woh; }
        float4 v = ((const float4*)src)[idx];
        uint32_t h01 = packh(scale * v.x, scale * v.y);
        uint32_t h23 = packh(scale * v.z, scale * v.w);
        ((uint2*)oh)[idx] = make_uint2(h01, h23);
    }
}

// =====================================================================
// HMMA projection: CTA tile M=64 x N=64, 2 warps (each m32 x n64),
// 64 thr, K=512 in 16 chunks; 2 passes W_h·X_h + W_h·X_l;
// TRIPLE-buffered cp.async (2 stages in flight); 5 CTAs/SM
// =====================================================================
#define WP  80       // W row pitch bytes (32 fp16 + pad)
#define XP  144      // X row pitch bytes (64 fp16 + pad)
#define P_WH 0
#define P_XH 5120
#define P_XL 9728
#define PB   14336
#define PROJ_SMEM (3 * PB)   // 43008

__device__ __forceinline__ void proj_core(
    uint32_t sb, int tid, int lane, int wm, int n0, int c0,
    const __half* __restrict__ Wh,
    const __half* __restrict__ Xh, const __half* __restrict__ Xl,
    float S[2][8][4])
{
    auto stage = [&](uint32_t b, int k0) {
        for (int i = tid; i < 256; i += 64) {            // W: 64 rows x 4 chunks
            int row = i >> 2, ch = i & 3;
            size_t off = (size_t)(c0 + row) * C_DIM + k0 + ch * 8;
            CP16(b + P_WH + row * WP + ch * 16, Wh + off);
        }
        for (int i = tid; i < 256; i += 64) {            // X: 32 rows x 8 chunks
            int row = i >> 3, ch = i & 7;
            size_t off = (size_t)(k0 + row) * N_TOK + n0 + ch * 8;
            uint32_t d = b + row * XP + ch * 16;
            CP16(d + P_XH, Xh + off);
            CP16(d + P_XL, Xl + off);
        }
    };

    stage(sb, 0);           CP_COMMIT();
    stage(sb + PB, 32);     CP_COMMIT();

    const int rb = ((lane >> 3) & 1) * 8 + (lane & 7);
    const int cb = ((lane >> 4) & 1) * 8;

    int bcur = 0;
    for (int kc = 0; kc < 16; kc++) {
        uint32_t cur = sb + bcur * PB;
        int bnxt2 = bcur + 2; if (bnxt2 >= 3) bnxt2 -= 3;
        stage(sb + bnxt2 * PB, ((kc + 2) & 15) * 32); CP_COMMIT();
        CP_WAIT2();
        __syncthreads();
#pragma unroll
        for (int kk = 0; kk < 2; kk++) {
            uint32_t ah[2][4];
#pragma unroll
            for (int mt = 0; mt < 2; mt++) {
                uint32_t aaddr = cur + (wm * 32 + mt * 16 + (lane & 15)) * WP
                               + kk * 32 + (lane >> 4) * 16;
                LDSM4(ah[mt], aaddr + P_WH);
            }
            uint32_t bh[4][4], bl[4][4];
#pragma unroll
            for (int nt2 = 0; nt2 < 4; nt2++) {
                uint32_t baddr = cur + (kk * 16 + rb) * XP + (nt2 * 16 + cb) * 2;
                LDSM4T(bh[nt2], baddr + P_XH);
                LDSM4T(bl[nt2], baddr + P_XL);
            }
#pragma unroll
            for (int mt = 0; mt < 2; mt++)
#pragma unroll
                for (int nt = 0; nt < 8; nt++)
                    MMA(S[mt][nt], ah[mt], (&bh[nt >> 1][(nt & 1) * 2]));
#pragma unroll
            for (int mt = 0; mt < 2; mt++)
#pragma unroll
                for (int nt = 0; nt < 8; nt++)
                    MMA(S[mt][nt], ah[mt], (&bl[nt >> 1][(nt & 1) * 2]));
        }
        __syncthreads();
        bcur++; if (bcur >= 3) bcur -= 3;
    }
}

// q/k/v projections fused (blockIdx.z selects); q writes hi only
__global__ __launch_bounds__(64, 5) void proj_qkv(
    const float* __restrict__ q_b, const float* __restrict__ k_b,
    const float* __restrict__ v_b)
{
    extern __shared__ char smch[];
    const uint32_t sb = smem_u32(smch);
    const int tid = threadIdx.x, lane = tid & 31, wm = tid >> 5;
    const int n0 = blockIdx.x * 64, c0 = blockIdx.y * 64;
    const int z = blockIdx.z;

    const __half* Wh; const float* bias; float bscale = 1.0f;
    __half *Yh, *Yl;
    if (z == 0)      { Wh = g_wqh; bias = q_b; Yh = g_qh; Yl = nullptr; }
    else if (z == 1) { Wh = g_wkh; bias = k_b; Yh = g_kh; Yl = g_kl; bscale = KSCALE; }
    else             { Wh = g_wvh; bias = v_b; Yh = g_vh; Yl = g_vl; }

    float S[2][8][4];
#pragma unroll
    for (int mt = 0; mt < 2; mt++)
#pragma unroll
        for (int nt = 0; nt < 8; nt++)
#pragma unroll
            for (int j = 0; j < 4; j++) S[mt][nt][j] = 0.0f;

    proj_core(sb, tid, lane, wm, n0, c0, Wh, g_xh, g_xl, S);

#pragma unroll
    for (int mt = 0; mt < 2; mt++) {
        const int crow0 = c0 + wm * 32 + mt * 16 + (lane >> 2);
        const float b0 = bscale * bias[crow0];
        const float b1 = bscale * bias[crow0 + 8];
#pragma unroll
        for (int nt = 0; nt < 8; nt++) {
            int col = n0 + nt * 8 + 2 * (lane & 3);
            float y0 = S[mt][nt][0] + b0, y1 = S[mt][nt][1] + b0;
            float y2 = S[mt][nt][2] + b1, y3 = S[mt][nt][3] + b1;
            uint32_t h01 = packh(y0, y1), h23 = packh(y2, y3);
            *(uint32_t*)&Yh[(size_t)crow0 * N_TOK + col] = h01;
            *(uint32_t*)&Yh[(size_t)(crow0 + 8) * N_TOK + col] = h23;
            if (Yl) {
                uint32_t l01 = packh(y0 - hlo(h01), y1 - hhi(h01));
                uint32_t l23 = packh(y2 - hlo(h23), y3 - hhi(h23));
                *(uint32_t*)&Yl[(size_t)crow0 * N_TOK + col] = l01;
                *(uint32_t*)&Yl[(size_t)(crow0 + 8) * N_TOK + col] = l23;
            }
        }
    }
}

// o-projection: f32 output to d_out
__global__ __launch_bounds__(64, 5) void proj_o(
    const float* __restrict__ bias, float* __restrict__ Yf)
{
    extern __shared__ char smch[];
    const uint32_t sb = smem_u32(smch);
    const int tid = threadIdx.x, lane = tid & 31, wm = tid >> 5;
    const int n0 = blockIdx.x * 64, c0 = blockIdx.y * 64;

    float S[2][8][4];
#pragma unroll
    for (int mt = 0; mt < 2; mt++)
#pragma unroll
        for (int nt = 0; nt < 8; nt++)
#pragma unroll
            for (int j = 0; j < 4; j++) S[mt][nt][j] = 0.0f;

    proj_core(sb, tid, lane, wm, n0, c0, g_woh, g_sh, g_sl, S);

#pragma unroll
    for (int mt = 0; mt < 2; mt++) {
        const int crow0 = c0 + wm * 32 + mt * 16 + (lane >> 2);
        const float b0 = bias[crow0];
        const float b1 = bias[crow0 + 8];
#pragma unroll
        for (int nt = 0; nt < 8; nt++) {
            int col = n0 + nt * 8 + 2 * (lane & 3);
            *(float2*)&Yf[(size_t)crow0 * N_TOK + col] =
                make_float2(S[mt][nt][0] + b0, S[mt][nt][1] + b0);
            *(float2*)&Yf[(size_t)(crow0 + 8) * N_TOK + col] =
                make_float2(S[mt][nt][2] + b1, S[mt][nt][3] + b1);
        }
    }
}

// =====================================================================
// flash attention: 4 warps x q32 (q128/CTA), kv64 iters, double-buffered,
// no-max softmax, ex2; 2 CTAs/SM; Q_hi frags in regs
// QK 2-pass (Qh·Kh + Qh·Kl), PV 2-pass (Vh·P + Vl·P)
// =====================================================================
#define QROWB 272
#define ROWB  144
#define S_QH 0
#define S_KV0 17408
#define KVB   36864
#define ATTN_SMEM (S_KV0 + 2 * KVB)   // 91136

__global__ __launch_bounds__(128, 2) void attn_mma()
{
    extern __shared__ char smch[];
    const uint32_t sb = smem_u32(smch);
    const int tid = threadIdx.x, lane = tid & 31, warp = tid >> 5;
    const int head = blockIdx.y;
    const int r0 = blockIdx.x * 128;

    const size_t hbase = (size_t)head * HDIM * N_TOK;
    const __half* qhp = g_qh + hbase + r0;
    const __half* khp = g_kh + hbase;
    const __half* klp = g_kl + hbase;
    const __half* vhp = g_vh + hbase;
    const __half* vlp = g_vl + hbase;

    auto stage_kv = [&](uint32_t dst, int c0) {
        for (int i = tid; i < 512; i += 128) {
            int row = i >> 3, ch = i & 7;
            size_t off = (size_t)row * N_TOK + c0 + ch * 8;
            uint32_t d = dst + row * ROWB + ch * 16;
            CP16(d,         khp + off);
            CP16(d +  9216, klp + off);
            CP16(d + 18432, vhp + off);
            CP16(d + 27648, vlp + off);
        }
    };

    for (int i = tid; i < 1024; i += 128) {
        int row = i >> 4, ch = i & 15;
        CP16(sb + S_QH + row * QROWB + ch * 16, qhp + (size_t)row * N_TOK + ch * 8);
    }
    stage_kv(sb + S_KV0, 0);
    CP_COMMIT();
    CP_WAIT0();
    __syncthreads();

    const int sl0 = 8 * (lane & 3);
    const int sl1 = sl0 + 4;
    const int rbq = ((lane >> 4) & 1) * 8 + (lane & 7);
    const int rb  = ((lane >> 3) & 1) * 8 + (lane & 7);
    const int cb  = ((lane >> 4) & 1) * 8;

    // ---- Q_hi a-frags persistent in registers (32 regs) ----
    uint32_t qa_h[2][4][4];
#pragma unroll
    for (int kk = 0; kk < 4; kk++)
#pragma unroll
        for (int mt = 0; mt < 2; mt++) {
            uint32_t cbq = warp * 32 + mt * 16 + ((lane >> 3) & 1) * 8;
            LDSM4T(qa_h[mt][kk], sb + S_QH + (kk * 16 + rbq) * QROWB + cbq * 2);
        }

    float l[2][2] = {};
    float ot[4][4][4];   // [d-tile][q8-tile][c]
#pragma unroll
    for (int m = 0; m < 4; m++)
#pragma unroll
        for (int n = 0; n < 4; n++)
#pragma unroll
            for (int j = 0; j < 4; j++) ot[m][n][j] = 0.0f;

    for (int it = 0; it < 64; it++) {
        uint32_t cur = sb + S_KV0 + (it & 1) * KVB;
        uint32_t nxt = sb + S_KV0 + ((it + 1) & 1) * KVB;
        stage_kv(nxt, ((it + 1) & 63) * 64);
        CP_COMMIT();
        CP_WAIT1();
        __syncthreads();

        // ---- S' = Q K^T (2-pass: Qh·Kh + Qh·Kl) ----
        float S[2][8][4];
#pragma unroll
        for (int mt = 0; mt < 2; mt++)
#pragma unroll
            for (int nt = 0; nt < 8; nt++)
#pragma unroll
                for (int j = 0; j < 4; j++) S[mt][nt][j] = 0.0f;
#pragma unroll
        for (int kk = 0; kk < 4; kk++) {
            uint32_t kb_h[4][4], kb_l[4][4];
#pragma unroll
            for (int nt2 = 0; nt2 < 4; nt2++) {
                uint32_t a = cur + (kk * 16 + rb) * ROWB + (nt2 * 16 + cb) * 2;
                LDSM4T(kb_h[nt2], a);
                LDSM4T(kb_l[nt2], a + 9216);
            }
#pragma unroll
            for (int mt = 0; mt < 2; mt++)
#pragma unroll
                for (int nt = 0; nt < 8; nt++)
                    MMA(S[mt][nt], qa_h[mt][kk], (&kb_h[nt >> 1][(nt & 1) * 2]));
#pragma unroll
            for (int mt = 0; mt < 2; mt++)
#pragma unroll
                for (int nt = 0; nt < 8; nt++)
                    MMA(S[mt][nt], qa_h[mt][kk], (&kb_l[nt >> 1][(nt & 1) * 2]));
        }

        // ---- p = 2^S' -> P_hi b-frags ----
        uint32_t pb[4][4][2];
#pragma unroll
        for (int mt = 0; mt < 2; mt++) {
#pragma unroll
            for (int nt = 0; nt < 8; nt++) {
                float p0 = ex2f(S[mt][nt][0]);
                float p1 = ex2f(S[mt][nt][1]);
                float p2 = ex2f(S[mt][nt][2]);
                float p3 = ex2f(S[mt][nt][3]);
                l[mt][0] += p0 + p1; l[mt][1] += p2 + p3;
                pb[mt * 2 + 0][nt >> 1][nt & 1] = packh(p0, p1);
                pb[mt * 2 + 1][nt >> 1][nt & 1] = packh(p2, p3);
            }
        }

        // ---- O^T += V P (2-pass: Vh·P + Vl·P) ----
#pragma unroll
        for (int kt = 0; kt < 4; kt++) {
            uint32_t va_h[4][4], va_l[4][4];
#pragma unroll
            for (int m = 0; m < 4; m++) {
                uint32_t a = cur + 18432 + (m * 16 + rb) * ROWB + (kt * 16 + cb) * 2;
                LDSM4(va_h[m], a);
                LDSM4(va_l[m], a + 9216);
            }
#pragma unroll
            for (int m = 0; m < 4; m++)
#pragma unroll
                for (int nq = 0; nq < 4; nq++)
                    MMA(ot[m][nq], va_h[m], pb[nq][kt]);
#pragma unroll
            for (int m = 0; m < 4; m++)
#pragma unroll
                for (int nq = 0; nq < 4; nq++)
                    MMA(ot[m][nq], va_l[m], pb[nq][kt]);
        }
        __syncthreads();
    }

    // ---- reduce row sums, normalize, write fp16 hi/lo (C, N) ----
#pragma unroll
    for (int mt = 0; mt < 2; mt++)
#pragma unroll
        for (int h2 = 0; h2 < 2; h2++) {
            l[mt][h2] += __shfl_xor_sync(0xffffffffu, l[mt][h2], 1);
            l[mt][h2] += __shfl_xor_sync(0xffffffffu, l[mt][h2], 2);
        }

    float inv0[4], inv1[4];
#pragma unroll
    for (int nq = 0; nq < 4; nq++) {
        float lv = l[nq >> 1][nq & 1];
        inv0[nq] = 1.0f / __shfl_sync(0xffffffffu, lv, sl0);
        inv1[nq] = 1.0f / __shfl_sync(0xffffffffu, lv, sl1);
    }

#pragma unroll
    for (int m = 0; m < 4; m++) {
        int drow = head * HDIM + m * 16 + (lane >> 2);
#pragma unroll
        for (int nq = 0; nq < 4; nq++) {
            int col = r0 + warp * 32 + nq * 8 + 2 * (lane & 3);
            float y0, y1; uint32_t h, lo;

            y0 = ot[m][nq][0] * inv0[nq]; y1 = ot[m][nq][1] * inv1[nq];
            h = packh(y0, y1); lo = packh(y0 - hlo(h), y1 - hhi(h));
            *(uint32_t*)&g_sh[(size_t)drow * N_TOK + col] = h;
            *(uint32_t*)&g_sl[(size_t)drow * N_TOK + col] = lo;

            y0 = ot[m][nq][2] * inv0[nq]; y1 = ot[m][nq][3] * inv1[nq];
            h = packh(y0, y1); lo = packh(y0 - hlo(h), y1 - hhi(h));
            *(uint32_t*)&g_sh[(size_t)(drow + 8) * N_TOK + col] = h;
            *(uint32_t*)&g_sl[(size_t)(drow + 8) * N_TOK + col] = lo;
        }
    }
}

// ---------------- launch ----------------
extern "C" void kernel_launch(void* const* d_in, const int* in_sizes, int n_in,
                              void* d_out, int out_size)
{
    const float* x   = (const float*)d_in[0];
    const float* q_w = (const float*)d_in[1];
    const float* q_b = (const float*)d_in[2];
    const float* k_w = (const float*)d_in[3];
    const float* k_b = (const float*)d_in[4];
    const float* v_w = (const float*)d_in[5];
    const float* v_b = (const float*)d_in[6];
    const float* o_w = (const float*)d_in[7];
    const float* o_b = (const float*)d_in[8];
    float* out = (float*)d_out;

    cudaFuncSetAttribute(attn_mma, cudaFuncAttributeMaxDynamicSharedMemorySize, ATTN_SMEM);
    cudaFuncSetAttribute(proj_qkv, cudaFuncAttributeMaxDynamicSharedMemorySize, PROJ_SMEM);
    cudaFuncSetAttribute(proj_o,   cudaFuncAttributeMaxDynamicSharedMemorySize, PROJ_SMEM);

    const int nsplit = NX4 + 4 * NW4;   // 786432
    split_all<<<nsplit / 256, 256>>>(x, q_w, k_w, v_w, o_w);

    dim3 gqkv(N_TOK / 64, C_DIM / 64, 3);   // (64, 8, 3) = 1536
    proj_qkv<<<gqkv, 64, PROJ_SMEM>>>(q_b, k_b, v_b);

    dim3 gattn(N_TOK / 128, HEADS);         // (32, 8)
    attn_mma<<<gattn, 128, ATTN_SMEM>>>();

    dim3 gproj(N_TOK / 64, C_DIM / 64);     // (64, 8) = 512
    proj_o<<<gproj, 64, PROJ_SMEM>>>(o_b, out);
}